// round 4
// baseline (speedup 1.0000x reference)
#include <cuda_runtime.h>
#include <math.h>
#include <stdint.h>

// ---------------------------------------------------------------------------
// Problem constants
//   B=4, SEQ=1024, DIM=1024, HEADS=16, HD=64, N_EXP=2, SLOTS=512, HID=4096
// Output: [ y : 4*1024*1024 f32 ][ attn : 4*1024*1024*16 f32 ]
// ---------------------------------------------------------------------------

#define OFF_Q       0LL
#define OFF_KV      4194304LL
#define OFF_TMP     12582912LL     // attn E=exp(S) scratch (b,h,n,m) 64M floats
#define OFF_ATTOUT  79691776LL
#define OFF_PROJ    83886080LL
#define OFF_X1      88080384LL
#define OFF_LOGITS  92274688LL
#define OFF_DISPT   96468992LL
#define OFF_COMB    100663296LL
#define OFF_SLOTS   104857600LL
#define OFF_H       109051904LL    // 16M floats
#define OFF_YMOE    125829120LL
#define OFF_MOE     130023424LL
#define OFF_RL      134283264LL
#define ARENA_FLOATS 134348800LL

__device__ float g_arena[ARENA_FLOATS];

__device__ __forceinline__ float gelu_tanh(float v) {
    const float c0 = 0.7978845608028654f;   // sqrt(2/pi)
    float t = tanhf(c0 * (v + 0.044715f * v * v * v));
    return 0.5f * v * (1.0f + t);
}

__device__ __forceinline__ float to_tf32(float x) {
    float r;
    asm("cvt.rna.tf32.f32 %0, %1;" : "=f"(r) : "f"(x));
    return r;
}

#define MMA_TF32(c0,c1,c2,c3,a0,a1,a2,a3,b0,b1)                               \
    asm volatile("mma.sync.aligned.m16n8k8.row.col.f32.tf32.tf32.f32 "        \
                 "{%0,%1,%2,%3},{%4,%5,%6,%7},{%8,%9},{%0,%1,%2,%3};"         \
                 : "+f"(c0), "+f"(c1), "+f"(c2), "+f"(c3)                     \
                 : "r"(a0), "r"(a1), "r"(a2), "r"(a3), "r"(b0), "r"(b1))

extern __shared__ float dynsm[];

// ---------------------------------------------------------------------------
// tf32 tensor-core batched GEMM, block tile 128x256, warp tile 64x64.
// C = A(MxK) @ B(KxN) [+bias] [gelu]; M mult 128, N mult 256, K mult 16.
// 256 threads = 8 warps (2m x 4n). Double-buffered smem (dynamic, 54.3KB).
// ---------------------------------------------------------------------------
__global__ void __launch_bounds__(256)
tgemm(const float* __restrict__ A, const float* __restrict__ Bm,
      const float* __restrict__ bias, float* __restrict__ C,
      int M, int N, int K,
      long long sA, long long sB, long long sBias, long long sC,
      int nBmod, int act)
{
    int z = blockIdx.z;
    int zb = nBmod ? (z % nBmod) : z;
    A  += (long long)z * sA;
    Bm += (long long)zb * sB;
    if (act >= 1) bias += (long long)zb * sBias;
    C  += (long long)z * sC;

    float* As = dynsm;                 // [2][128][20]
    float* Bs = dynsm + 2 * 128 * 20;  // [2][16][264]
#define AS(b,r,k) As[(b) * 2560 + (r) * 20 + (k)]
#define BS(b,r,n) Bs[(b) * 4224 + (r) * 264 + (n)]

    int bx = blockIdx.x, by = blockIdx.y;
    int tid = threadIdx.x;
    int wid = tid >> 5;
    int lane = tid & 31;
    int g = lane >> 2;
    int j = lane & 3;
    int wm64 = (wid >> 2) * 64;
    int wn64 = (wid & 3) * 64;

    int aRow = tid >> 1;             // 0..127
    int aKc  = (tid & 1) * 8;        // 0 or 8
    int bRow = tid >> 4;             // 0..15
    int bCc  = (tid & 15) * 16;      // 0..240

    const float* Ap = A + (long long)(by * 128 + aRow) * K + aKc;
    const float* Bp = Bm + (long long)bRow * N + bx * 256 + bCc;

    float c[4][8][4];
    #pragma unroll
    for (int mt = 0; mt < 4; mt++)
        #pragma unroll
        for (int nt = 0; nt < 8; nt++)
            #pragma unroll
            for (int r = 0; r < 4; r++) c[mt][nt][r] = 0.0f;

    float4 av0 = *(const float4*)Ap;
    float4 av1 = *(const float4*)(Ap + 4);
    float4 bv0 = *(const float4*)Bp;
    float4 bv1 = *(const float4*)(Bp + 4);
    float4 bv2 = *(const float4*)(Bp + 8);
    float4 bv3 = *(const float4*)(Bp + 12);

    // store tile 0
    {
        float4 t;
        t.x = to_tf32(av0.x); t.y = to_tf32(av0.y); t.z = to_tf32(av0.z); t.w = to_tf32(av0.w);
        *(float4*)&AS(0, aRow, aKc) = t;
        t.x = to_tf32(av1.x); t.y = to_tf32(av1.y); t.z = to_tf32(av1.z); t.w = to_tf32(av1.w);
        *(float4*)&AS(0, aRow, aKc + 4) = t;
        t.x = to_tf32(bv0.x); t.y = to_tf32(bv0.y); t.z = to_tf32(bv0.z); t.w = to_tf32(bv0.w);
        *(float4*)&BS(0, bRow, bCc) = t;
        t.x = to_tf32(bv1.x); t.y = to_tf32(bv1.y); t.z = to_tf32(bv1.z); t.w = to_tf32(bv1.w);
        *(float4*)&BS(0, bRow, bCc + 4) = t;
        t.x = to_tf32(bv2.x); t.y = to_tf32(bv2.y); t.z = to_tf32(bv2.z); t.w = to_tf32(bv2.w);
        *(float4*)&BS(0, bRow, bCc + 8) = t;
        t.x = to_tf32(bv3.x); t.y = to_tf32(bv3.y); t.z = to_tf32(bv3.z); t.w = to_tf32(bv3.w);
        *(float4*)&BS(0, bRow, bCc + 12) = t;
    }
    __syncthreads();

    int buf = 0;
    for (int k0 = 0; k0 < K; k0 += 16) {
        bool notlast = (k0 + 16 < K);
        if (notlast) {
            Ap += 16;
            Bp += (long long)16 * N;
            av0 = *(const float4*)Ap;
            av1 = *(const float4*)(Ap + 4);
            bv0 = *(const float4*)Bp;
            bv1 = *(const float4*)(Bp + 4);
            bv2 = *(const float4*)(Bp + 8);
            bv3 = *(const float4*)(Bp + 12);
        }
        #pragma unroll
        for (int kk = 0; kk < 16; kk += 8) {
            uint32_t a[4][4];
            uint32_t bfr[8][2];
            #pragma unroll
            for (int mt = 0; mt < 4; mt++) {
                const float* p = &AS(buf, wm64 + mt * 16 + g, kk + j);
                a[mt][0] = __float_as_uint(p[0]);
                a[mt][1] = __float_as_uint(p[8 * 20]);
                a[mt][2] = __float_as_uint(p[4]);
                a[mt][3] = __float_as_uint(p[8 * 20 + 4]);
            }
            #pragma unroll
            for (int nt = 0; nt < 8; nt++) {
                const float* p = &BS(buf, kk + j, wn64 + nt * 8 + g);
                bfr[nt][0] = __float_as_uint(p[0]);
                bfr[nt][1] = __float_as_uint(p[4 * 264]);
            }
            #pragma unroll
            for (int mt = 0; mt < 4; mt++)
                #pragma unroll
                for (int nt = 0; nt < 8; nt++)
                    MMA_TF32(c[mt][nt][0], c[mt][nt][1], c[mt][nt][2], c[mt][nt][3],
                             a[mt][0], a[mt][1], a[mt][2], a[mt][3],
                             bfr[nt][0], bfr[nt][1]);
        }
        if (notlast) {
            int nb = buf ^ 1;
            float4 t;
            t.x = to_tf32(av0.x); t.y = to_tf32(av0.y); t.z = to_tf32(av0.z); t.w = to_tf32(av0.w);
            *(float4*)&AS(nb, aRow, aKc) = t;
            t.x = to_tf32(av1.x); t.y = to_tf32(av1.y); t.z = to_tf32(av1.z); t.w = to_tf32(av1.w);
            *(float4*)&AS(nb, aRow, aKc + 4) = t;
            t.x = to_tf32(bv0.x); t.y = to_tf32(bv0.y); t.z = to_tf32(bv0.z); t.w = to_tf32(bv0.w);
            *(float4*)&BS(nb, bRow, bCc) = t;
            t.x = to_tf32(bv1.x); t.y = to_tf32(bv1.y); t.z = to_tf32(bv1.z); t.w = to_tf32(bv1.w);
            *(float4*)&BS(nb, bRow, bCc + 4) = t;
            t.x = to_tf32(bv2.x); t.y = to_tf32(bv2.y); t.z = to_tf32(bv2.z); t.w = to_tf32(bv2.w);
            *(float4*)&BS(nb, bRow, bCc + 8) = t;
            t.x = to_tf32(bv3.x); t.y = to_tf32(bv3.y); t.z = to_tf32(bv3.z); t.w = to_tf32(bv3.w);
            *(float4*)&BS(nb, bRow, bCc + 12) = t;
            __syncthreads();
            buf = nb;
        }
    }

    // epilogue
    #pragma unroll
    for (int mt = 0; mt < 4; mt++) {
        int r0 = by * 128 + wm64 + mt * 16 + g;
        #pragma unroll
        for (int nt = 0; nt < 8; nt++) {
            int col = bx * 256 + wn64 + nt * 8 + 2 * j;
            float b0 = 0.0f, b1 = 0.0f;
            if (act >= 1) { b0 = bias[col]; b1 = bias[col + 1]; }
            float v0 = c[mt][nt][0] + b0;
            float v1 = c[mt][nt][1] + b1;
            float v2 = c[mt][nt][2] + b0;
            float v3 = c[mt][nt][3] + b1;
            if (act == 2) {
                v0 = gelu_tanh(v0); v1 = gelu_tanh(v1);
                v2 = gelu_tanh(v2); v3 = gelu_tanh(v3);
            }
            *(float2*)(C + (long long)r0 * N + col)       = make_float2(v0, v1);
            *(float2*)(C + (long long)(r0 + 8) * N + col) = make_float2(v2, v3);
        }
    }
#undef AS
#undef BS
}

// ---------------------------------------------------------------------------
// Fused attention (tensor cores): per (b,h), n-tile 64.
// S = (0.125*Q)K^T; E = exp(S) -> tmp (unnormalized); O = (E@V)/rowsum.
// No max subtraction (logits small; exact softmax identity).
// Dynamic smem: Qs(64x68) Kt(64x68) Vs(64x72) Ps(64x68) sums(4x64) = 71.7KB
// ---------------------------------------------------------------------------
__global__ void __launch_bounds__(256)
att_fused(const float* __restrict__ q, const float* __restrict__ kv,
          float* __restrict__ tmp, float* __restrict__ rowrl,
          float* __restrict__ attout)
{
    int bh = blockIdx.y;
    int b = bh >> 4, h = bh & 15;
    int n0 = blockIdx.x * 64;

    float* Qs   = dynsm;            // [n][d] pad 68
    float* Kt   = dynsm + 4352;     // [m][d] pad 68
    float* Vs   = dynsm + 8704;     // [m][d] pad 72
    float* Ps   = dynsm + 13312;    // [n][m] pad 68
    float* sums = dynsm + 17664;    // [4][64]

    int tid = threadIdx.x, lane = tid & 31, wid = tid >> 5;
    int g = lane >> 2, j = lane & 3;
    int wm32 = (wid >> 2) * 32;
    int wn16 = (wid & 3) * 16;

    sums[tid & 255] = 0.0f;

    for (int i = tid; i < 1024; i += 256) {
        int r = i >> 4, c4 = (i & 15) * 4;
        float4 v = *(const float4*)(q + ((size_t)(b * 1024 + n0 + r) * 1024) + h * 64 + c4);
        float4 t;
        t.x = to_tf32(v.x * 0.125f); t.y = to_tf32(v.y * 0.125f);
        t.z = to_tf32(v.z * 0.125f); t.w = to_tf32(v.w * 0.125f);
        *(float4*)&Qs[r * 68 + c4] = t;
    }

    float o[2][2][4];
    #pragma unroll
    for (int mt = 0; mt < 2; mt++)
        #pragma unroll
        for (int nt = 0; nt < 2; nt++)
            #pragma unroll
            for (int r = 0; r < 4; r++) o[mt][nt][r] = 0.0f;

    for (int m0 = 0; m0 < 1024; m0 += 64) {
        __syncthreads();
        for (int i = tid; i < 1024; i += 256) {
            int r = i >> 4, c4 = (i & 15) * 4;
            const float* kb = kv + ((size_t)(b * 1024 + m0 + r) * 2048) + h * 64 + c4;
            float4 kvv = *(const float4*)kb;
            float4 t;
            t.x = to_tf32(kvv.x); t.y = to_tf32(kvv.y);
            t.z = to_tf32(kvv.z); t.w = to_tf32(kvv.w);
            *(float4*)&Kt[r * 68 + c4] = t;
            float4 vv = *(const float4*)(kb + 1024);
            t.x = to_tf32(vv.x); t.y = to_tf32(vv.y);
            t.z = to_tf32(vv.z); t.w = to_tf32(vv.w);
            *(float4*)&Vs[r * 72 + c4] = t;
        }
        __syncthreads();

        // S-mma
        float c[2][2][4];
        #pragma unroll
        for (int mt = 0; mt < 2; mt++)
            #pragma unroll
            for (int nt = 0; nt < 2; nt++)
                #pragma unroll
                for (int r = 0; r < 4; r++) c[mt][nt][r] = 0.0f;

        #pragma unroll
        for (int kk = 0; kk < 64; kk += 8) {
            uint32_t a[2][4], bf[2][2];
            #pragma unroll
            for (int mt = 0; mt < 2; mt++) {
                const float* p = &Qs[(wm32 + mt * 16 + g) * 68 + kk + j];
                a[mt][0] = __float_as_uint(p[0]);
                a[mt][1] = __float_as_uint(p[8 * 68]);
                a[mt][2] = __float_as_uint(p[4]);
                a[mt][3] = __float_as_uint(p[8 * 68 + 4]);
            }
            #pragma unroll
            for (int nt = 0; nt < 2; nt++) {
                const float* p = &Kt[(wn16 + nt * 8 + g) * 68 + kk + j];
                bf[nt][0] = __float_as_uint(p[0]);
                bf[nt][1] = __float_as_uint(p[4]);
            }
            #pragma unroll
            for (int mt = 0; mt < 2; mt++)
                #pragma unroll
                for (int nt = 0; nt < 2; nt++)
                    MMA_TF32(c[mt][nt][0], c[mt][nt][1], c[mt][nt][2], c[mt][nt][3],
                             a[mt][0], a[mt][1], a[mt][2], a[mt][3],
                             bf[nt][0], bf[nt][1]);
        }

        // E = exp(S): write tmp + Ps, accumulate row sums
        #pragma unroll
        for (int mt = 0; mt < 2; mt++) {
            int r1 = wm32 + mt * 16 + g;
            float eA = 0.0f, eB = 0.0f;
            #pragma unroll
            for (int nt = 0; nt < 2; nt++) {
                int col = wn16 + nt * 8 + 2 * j;
                float e0 = __expf(c[mt][nt][0]);
                float e1 = __expf(c[mt][nt][1]);
                float e2 = __expf(c[mt][nt][2]);
                float e3 = __expf(c[mt][nt][3]);
                float* base = tmp + ((size_t)bh * 1024 + n0 + r1) * 1024 + m0 + col;
                *(float2*)base              = make_float2(e0, e1);
                *(float2*)(base + 8 * 1024) = make_float2(e2, e3);
                *(float2*)&Ps[r1 * 68 + col]       = make_float2(to_tf32(e0), to_tf32(e1));
                *(float2*)&Ps[(r1 + 8) * 68 + col] = make_float2(to_tf32(e2), to_tf32(e3));
                eA += e0 + e1;
                eB += e2 + e3;
            }
            eA += __shfl_xor_sync(0xffffffffu, eA, 1);
            eA += __shfl_xor_sync(0xffffffffu, eA, 2);
            eB += __shfl_xor_sync(0xffffffffu, eB, 1);
            eB += __shfl_xor_sync(0xffffffffu, eB, 2);
            if (j == 0) {
                sums[(wn16 >> 4) * 64 + r1]     += eA;
                sums[(wn16 >> 4) * 64 + r1 + 8] += eB;
            }
        }
        __syncthreads();

        // PV-mma: A = Ps (E), B = Vs
        #pragma unroll
        for (int kk = 0; kk < 64; kk += 8) {
            uint32_t a[2][4], bf[2][2];
            #pragma unroll
            for (int mt = 0; mt < 2; mt++) {
                const float* p = &Ps[(wm32 + mt * 16 + g) * 68 + kk + j];
                a[mt][0] = __float_as_uint(p[0]);
                a[mt][1] = __float_as_uint(p[8 * 68]);
                a[mt][2] = __float_as_uint(p[4]);
                a[mt][3] = __float_as_uint(p[8 * 68 + 4]);
            }
            #pragma unroll
            for (int nt = 0; nt < 2; nt++) {
                const float* p = &Vs[(kk + j) * 72 + wn16 + nt * 8 + g];
                bf[nt][0] = __float_as_uint(p[0]);
                bf[nt][1] = __float_as_uint(p[4 * 72]);
            }
            #pragma unroll
            for (int mt = 0; mt < 2; mt++)
                #pragma unroll
                for (int nt = 0; nt < 2; nt++)
                    MMA_TF32(o[mt][nt][0], o[mt][nt][1], o[mt][nt][2], o[mt][nt][3],
                             a[mt][0], a[mt][1], a[mt][2], a[mt][3],
                             bf[nt][0], bf[nt][1]);
        }
    }

    __syncthreads();
    if (tid < 64) {
        float tot = sums[tid] + sums[64 + tid] + sums[128 + tid] + sums[192 + tid];
        float r = 1.0f / tot;
        sums[tid] = r;                                 // reuse as reciprocal
        rowrl[(size_t)bh * 1024 + n0 + tid] = r;
    }
    __syncthreads();

    #pragma unroll
    for (int mt = 0; mt < 2; mt++) {
        int r1 = wm32 + mt * 16 + g;
        float rlA = sums[r1], rlB = sums[r1 + 8];
        #pragma unroll
        for (int nt = 0; nt < 2; nt++) {
            int col = wn16 + nt * 8 + 2 * j;
            float* base = attout + ((size_t)(b * 1024 + n0 + r1) * 1024) + h * 64 + col;
            *(float2*)base              = make_float2(o[mt][nt][0] * rlA, o[mt][nt][1] * rlA);
            *(float2*)(base + 8 * 1024) = make_float2(o[mt][nt][2] * rlB, o[mt][nt][3] * rlB);
        }
    }
}

// ---------------------------------------------------------------------------
// Normalize + transpose: out(b,n,m,h) = E(b,h,n,m) * rl(b,h,n).
// ---------------------------------------------------------------------------
__global__ void attn_tr(const float* __restrict__ tmp, const float* __restrict__ rowrl,
                        float* __restrict__ outAttn)
{
    int b = blockIdx.z;
    int n = blockIdx.y;
    int m0 = blockIdx.x * 256;
    __shared__ float T[16][257];
    __shared__ float rl_s[16];
    int tid = threadIdx.x;
    if (tid < 16) rl_s[tid] = rowrl[(size_t)(b * 16 + tid) * 1024 + n];
    __syncthreads();
    for (int i = tid; i < 16 * 256; i += 256) {
        int hh = i >> 8, mm = i & 255;
        T[hh][mm] = tmp[((size_t)(b * 16 + hh) * 1024 + n) * 1024 + m0 + mm] * rl_s[hh];
    }
    __syncthreads();
    float* dst = outAttn + ((size_t)(b * 1024 + n) * 1024 + m0 + tid) * 16;
    #pragma unroll
    for (int k = 0; k < 16; k += 4) {
        *(float4*)(dst + k) = make_float4(T[k][tid], T[k + 1][tid], T[k + 2][tid], T[k + 3][tid]);
    }
}

// ---------------------------------------------------------------------------
// Row softmax over contiguous 1024 (combine weights).
// ---------------------------------------------------------------------------
__global__ void row_softmax(const float* __restrict__ in, float* __restrict__ outp)
{
    size_t row = blockIdx.x;
    const float4* L = (const float4*)(in + row * 1024);
    float4* O = (float4*)(outp + row * 1024);
    int t = threadIdx.x;
    float4 v = L[t];
    float mx = fmaxf(fmaxf(v.x, v.y), fmaxf(v.z, v.w));
    __shared__ float smA[8], smB[8];
    #pragma unroll
    for (int off = 16; off; off >>= 1) mx = fmaxf(mx, __shfl_xor_sync(0xffffffffu, mx, off));
    if ((t & 31) == 0) smA[t >> 5] = mx;
    __syncthreads();
    mx = smA[0];
    #pragma unroll
    for (int w = 1; w < 8; w++) mx = fmaxf(mx, smA[w]);
    float e0 = __expf(v.x - mx), e1 = __expf(v.y - mx);
    float e2 = __expf(v.z - mx), e3 = __expf(v.w - mx);
    float s = e0 + e1 + e2 + e3;
    #pragma unroll
    for (int off = 16; off; off >>= 1) s += __shfl_xor_sync(0xffffffffu, s, off);
    if ((t & 31) == 0) smB[t >> 5] = s;
    __syncthreads();
    s = 0.0f;
    #pragma unroll
    for (int w = 0; w < 8; w++) s += smB[w];
    float r = 1.0f / s;
    O[t] = make_float4(e0 * r, e1 * r, e2 * r, e3 * r);
}

// ---------------------------------------------------------------------------
// Dispatch softmax over token axis n, written TRANSPOSED: dispT[b][es][n].
// ---------------------------------------------------------------------------
__global__ void disp_softmax(const float* __restrict__ logits, float* __restrict__ dispT)
{
    int b = blockIdx.y;
    int c0 = blockIdx.x * 64;
    const float* L = logits + (size_t)b * 1048576;
    float* O = dispT + (size_t)b * 1048576;
    int tid = threadIdx.x;
    int tx = tid & 63, ty = tid >> 6;   // 4 x 64
    int col = c0 + tx;

    __shared__ float red[4][64];
    float mx = -1e30f;
    for (int n = ty; n < 1024; n += 4) mx = fmaxf(mx, L[(size_t)n * 1024 + col]);
    red[ty][tx] = mx;
    __syncthreads();
    mx = fmaxf(fmaxf(red[0][tx], red[1][tx]), fmaxf(red[2][tx], red[3][tx]));
    __syncthreads();
    float s = 0.0f;
    for (int n = ty; n < 1024; n += 4) s += __expf(L[(size_t)n * 1024 + col] - mx);
    red[ty][tx] = s;
    __syncthreads();
    s = red[0][tx] + red[1][tx] + red[2][tx] + red[3][tx];
    float rinv = 1.0f / s;
    __syncthreads();

    __shared__ float T[64][65];
    for (int n0 = 0; n0 < 1024; n0 += 64) {
        for (int n = ty; n < 64; n += 4)
            T[tx][n] = __expf(L[(size_t)(n0 + n) * 1024 + col] - mx) * rinv;
        __syncthreads();
        int cl = tid >> 2;
        int nl = (tid & 3) * 16;
        float* dst = O + (size_t)(c0 + cl) * 1024 + n0 + nl;
        #pragma unroll
        for (int k = 0; k < 16; k += 4)
            *(float4*)(dst + k) = make_float4(T[cl][nl + k], T[cl][nl + k + 1],
                                              T[cl][nl + k + 2], T[cl][nl + k + 3]);
        __syncthreads();
    }
}

// ---------------------------------------------------------------------------
// Fused residual + LayerNorm: out = LN(a + coefb * bsrc) * g + beta
// ---------------------------------------------------------------------------
__global__ void ln_res(const float* __restrict__ a, const float* __restrict__ bsrc,
                       float coefb, const float* __restrict__ g,
                       const float* __restrict__ beta, float* __restrict__ outp)
{
    size_t row = blockIdx.x;
    int t = threadIdx.x;
    float4 av = ((const float4*)(a + row * 1024))[t];
    float4 bv = ((const float4*)(bsrc + row * 1024))[t];
    float x0 = av.x + coefb * bv.x;
    float x1 = av.y + coefb * bv.y;
    float x2 = av.z + coefb * bv.z;
    float x3 = av.w + coefb * bv.w;
    float s = x0 + x1 + x2 + x3;
    float q = x0 * x0 + x1 * x1 + x2 * x2 + x3 * x3;
    __shared__ float smA[8], smB[8];
    #pragma unroll
    for (int off = 16; off; off >>= 1) {
        s += __shfl_xor_sync(0xffffffffu, s, off);
        q += __shfl_xor_sync(0xffffffffu, q, off);
    }
    if ((t & 31) == 0) { smA[t >> 5] = s; smB[t >> 5] = q; }
    __syncthreads();
    s = 0.0f; q = 0.0f;
    #pragma unroll
    for (int w = 0; w < 8; w++) { s += smA[w]; q += smB[w]; }
    float mu = s * (1.0f / 1024.0f);
    float var = q * (1.0f / 1024.0f) - mu * mu;
    float rs = rsqrtf(var + 1e-5f);
    float4 gv = ((const float4*)g)[t];
    float4 btv = ((const float4*)beta)[t];
    float4 out4;
    out4.x = (x0 - mu) * rs * gv.x + btv.x;
    out4.y = (x1 - mu) * rs * gv.y + btv.y;
    out4.z = (x2 - mu) * rs * gv.z + btv.z;
    out4.w = (x3 - mu) * rs * gv.w + btv.w;
    ((float4*)(outp + row * 1024))[t] = out4;
}

// ---------------------------------------------------------------------------
// Launcher
// ---------------------------------------------------------------------------
extern "C" void kernel_launch(void* const* d_in, const int* in_sizes, int n_in,
                              void* d_out, int out_size)
{
    const float* x   = (const float*)d_in[0];
    const float* Wq  = (const float*)d_in[1];
    const float* bq  = (const float*)d_in[2];
    const float* Wkv = (const float*)d_in[3];
    const float* bkv = (const float*)d_in[4];
    const float* Wp  = (const float*)d_in[5];
    const float* bp  = (const float*)d_in[6];
    const float* g1  = (const float*)d_in[7];
    const float* b1  = (const float*)d_in[8];
    const float* phi = (const float*)d_in[9];
    const float* We1 = (const float*)d_in[10];
    const float* be1 = (const float*)d_in[11];
    const float* We2 = (const float*)d_in[12];
    const float* be2 = (const float*)d_in[13];
    const float* g2  = (const float*)d_in[14];
    const float* b2  = (const float*)d_in[15];

    float* arena = nullptr;
    cudaGetSymbolAddress((void**)&arena, g_arena);

    float* q      = arena + OFF_Q;
    float* kvb    = arena + OFF_KV;
    float* tmp    = arena + OFF_TMP;
    float* attout = arena + OFF_ATTOUT;
    float* proj   = arena + OFF_PROJ;
    float* x1     = arena + OFF_X1;
    float* logits = arena + OFF_LOGITS;
    float* dispT  = arena + OFF_DISPT;
    float* comb   = arena + OFF_COMB;
    float* slots  = arena + OFF_SLOTS;
    float* hbuf   = arena + OFF_H;
    float* ymoe   = arena + OFF_YMOE;
    float* moeout = arena + OFF_MOE;
    float* rl     = arena + OFF_RL;

    float* out = (float*)d_out;
    float* outAttn = out + 4194304;

    const int GEMM_SMEM = 54272;   // 2*128*20 + 2*16*264 floats
    const int ATT_SMEM  = 71680;   // Qs+Kt+Vs+Ps+sums
    cudaFuncSetAttribute(tgemm, cudaFuncAttributeMaxDynamicSharedMemorySize, GEMM_SMEM);
    cudaFuncSetAttribute(att_fused, cudaFuncAttributeMaxDynamicSharedMemorySize, ATT_SMEM);

    dim3 T(256);

    // q = x @ Wq + bq          (4096x1024x1024)
    tgemm<<<dim3(4, 32, 1), T, GEMM_SMEM>>>(x, Wq, bq, q, 4096, 1024, 1024, 0, 0, 0, 0, 1, 1);
    // kv = x @ Wkv + bkv       (4096x2048x1024)
    tgemm<<<dim3(8, 32, 1), T, GEMM_SMEM>>>(x, Wkv, bkv, kvb, 4096, 2048, 1024, 0, 0, 0, 0, 1, 1);

    // fused attention + transpose
    att_fused<<<dim3(16, 64), T, ATT_SMEM>>>(q, kvb, tmp, rl, attout);
    attn_tr<<<dim3(4, 1024, 4), T>>>(tmp, rl, outAttn);

    // out-proj + residual LN
    tgemm<<<dim3(4, 32, 1), T, GEMM_SMEM>>>(attout, Wp, bp, proj, 4096, 1024, 1024, 0, 0, 0, 0, 1, 1);
    ln_res<<<4096, T>>>(proj, x, 1.0f, g1, b1, x1);

    // soft-MoE
    tgemm<<<dim3(4, 32, 1), T, GEMM_SMEM>>>(x1, phi, nullptr, logits, 4096, 1024, 1024, 0, 0, 0, 0, 1, 0);
    row_softmax<<<4096, T>>>(logits, comb);
    disp_softmax<<<dim3(16, 4), T>>>(logits, dispT);

    // slots[b] = dispT[b] @ x1[b]
    tgemm<<<dim3(4, 8, 4), T, GEMM_SMEM>>>(dispT, x1, nullptr, slots, 1024, 1024, 1024,
                                           1048576, 1048576, 0, 1048576, 0, 0);
    // h = gelu(slots @ We1[e] + be1[e])
    tgemm<<<dim3(16, 4, 8), T, GEMM_SMEM>>>(slots, We1, be1, hbuf, 512, 4096, 1024,
                                            524288, 4194304, 4096, 2097152, 2, 2);
    // y = h @ We2[e] + be2[e]
    tgemm<<<dim3(4, 4, 8), T, GEMM_SMEM>>>(hbuf, We2, be2, ymoe, 512, 1024, 4096,
                                           2097152, 4194304, 1024, 524288, 2, 1);
    // moe_out[b] = comb[b] @ ymoe[b]
    tgemm<<<dim3(4, 8, 4), T, GEMM_SMEM>>>(comb, ymoe, nullptr, moeout, 1024, 1024, 1024,
                                           1048576, 1048576, 0, 1048576, 0, 0);

    // y = LN(moe_out + 2*x1)
    ln_res<<<4096, T>>>(moeout, x1, 2.0f, g2, b2, out);
}

// round 5
// speedup vs baseline: 1.9293x; 1.9293x over previous
#include <cuda_runtime.h>
#include <math.h>
#include <stdint.h>

// ---------------------------------------------------------------------------
// Problem constants
//   B=4, SEQ=1024, DIM=1024, HEADS=16, HD=64, N_EXP=2, SLOTS=512, HID=4096
// Output: [ y : 4*1024*1024 f32 ][ attn : 4*1024*1024*16 f32 ]
// ---------------------------------------------------------------------------

#define OFF_Q       0LL
#define OFF_KV      4194304LL
#define OFF_TMP     12582912LL     // attn E=exp(S) scratch (b,h,n,m) 64M floats
#define OFF_ATTOUT  79691776LL
#define OFF_PROJ    83886080LL
#define OFF_X1      88080384LL
#define OFF_LOGITS  92274688LL
#define OFF_DISPT   96468992LL
#define OFF_COMB    100663296LL
#define OFF_SLOTS   104857600LL
#define OFF_H       109051904LL    // 16M floats
#define OFF_YMOE    125829120LL
#define OFF_MOE     130023424LL
#define OFF_RL      134283264LL
#define ARENA_FLOATS 134348800LL

__device__ float g_arena[ARENA_FLOATS];

__device__ __forceinline__ float gelu_tanh(float v) {
    const float c0 = 0.7978845608028654f;   // sqrt(2/pi)
    float t = tanhf(c0 * (v + 0.044715f * v * v * v));
    return 0.5f * v * (1.0f + t);
}

__device__ __forceinline__ float to_tf32(float x) {
    float r;
    asm("cvt.rna.tf32.f32 %0, %1;" : "=f"(r) : "f"(x));
    return r;
}

#define MMA_TF32(c0,c1,c2,c3,a0,a1,a2,a3,b0,b1)                               \
    asm volatile("mma.sync.aligned.m16n8k8.row.col.f32.tf32.tf32.f32 "        \
                 "{%0,%1,%2,%3},{%4,%5,%6,%7},{%8,%9},{%0,%1,%2,%3};"         \
                 : "+f"(c0), "+f"(c1), "+f"(c2), "+f"(c3)                     \
                 : "r"(a0), "r"(a1), "r"(a2), "r"(a3), "r"(b0), "r"(b1))

extern __shared__ float dynsm[];

// ---------------------------------------------------------------------------
// tf32 tensor-core batched GEMM, double-buffered static smem.
// C = A(MxK) @ B(KxN) [+bias] [gelu]; M,N mult of 128, K mult of 16.
// 256 threads = 8 warps (2x4), warp tile 64x32, mma m16n8k8. (R3 version)
// ---------------------------------------------------------------------------
__global__ void __launch_bounds__(256, 2)
tgemm(const float* __restrict__ A, const float* __restrict__ Bm,
      const float* __restrict__ bias, float* __restrict__ C,
      int M, int N, int K,
      long long sA, long long sB, long long sBias, long long sC,
      int nBmod, int act)
{
    int z = blockIdx.z;
    int zb = nBmod ? (z % nBmod) : z;
    A  += (long long)z * sA;
    Bm += (long long)zb * sB;
    if (act >= 1) bias += (long long)zb * sBias;
    C  += (long long)z * sC;

    __shared__ float As[2][128][20];   // [m][k16 pad 20]
    __shared__ float Bs[2][16][136];   // [k][n128 pad 136]

    int bx = blockIdx.x, by = blockIdx.y;
    int tid = threadIdx.x;
    int wid = tid >> 5;
    int lane = tid & 31;
    int g = lane >> 2;
    int j = lane & 3;
    int wm64 = (wid >> 2) * 64;
    int wn32 = (wid & 3) * 32;

    int aRow0 = tid >> 2;            // 0..63
    int aKc   = (tid & 3) * 4;       // 0,4,8,12
    int bRow0 = tid >> 5;            // 0..7
    int bCc   = (tid & 31) * 4;      // 0..124

    const float* Ap0 = A + (long long)(by * 128 + aRow0)      * K + aKc;
    const float* Ap1 = A + (long long)(by * 128 + aRow0 + 64) * K + aKc;
    const float* Bp0 = Bm + (long long)(bRow0)     * N + bx * 128 + bCc;
    const float* Bp1 = Bm + (long long)(bRow0 + 8) * N + bx * 128 + bCc;

    float c[4][4][4];
    #pragma unroll
    for (int mt = 0; mt < 4; mt++)
        #pragma unroll
        for (int nt = 0; nt < 4; nt++)
            #pragma unroll
            for (int r = 0; r < 4; r++) c[mt][nt][r] = 0.0f;

    float4 av0 = *(const float4*)Ap0;
    float4 av1 = *(const float4*)Ap1;
    float4 bv0 = *(const float4*)Bp0;
    float4 bv1 = *(const float4*)Bp1;

    // store tile 0
    {
        float4 t;
        t.x = to_tf32(av0.x); t.y = to_tf32(av0.y); t.z = to_tf32(av0.z); t.w = to_tf32(av0.w);
        *(float4*)&As[0][aRow0][aKc] = t;
        t.x = to_tf32(av1.x); t.y = to_tf32(av1.y); t.z = to_tf32(av1.z); t.w = to_tf32(av1.w);
        *(float4*)&As[0][aRow0 + 64][aKc] = t;
        t.x = to_tf32(bv0.x); t.y = to_tf32(bv0.y); t.z = to_tf32(bv0.z); t.w = to_tf32(bv0.w);
        *(float4*)&Bs[0][bRow0][bCc] = t;
        t.x = to_tf32(bv1.x); t.y = to_tf32(bv1.y); t.z = to_tf32(bv1.z); t.w = to_tf32(bv1.w);
        *(float4*)&Bs[0][bRow0 + 8][bCc] = t;
    }
    __syncthreads();

    int buf = 0;
    for (int k0 = 0; k0 < K; k0 += 16) {
        bool notlast = (k0 + 16 < K);
        if (notlast) {
            Ap0 += 16; Ap1 += 16;
            Bp0 += (long long)16 * N; Bp1 += (long long)16 * N;
            av0 = *(const float4*)Ap0;
            av1 = *(const float4*)Ap1;
            bv0 = *(const float4*)Bp0;
            bv1 = *(const float4*)Bp1;
        }
        #pragma unroll
        for (int kk = 0; kk < 16; kk += 8) {
            uint32_t a[4][4];
            uint32_t bfr[4][2];
            #pragma unroll
            for (int mt = 0; mt < 4; mt++) {
                const float* p = &As[buf][wm64 + mt * 16 + g][kk + j];
                a[mt][0] = __float_as_uint(p[0]);
                a[mt][1] = __float_as_uint(p[8 * 20]);
                a[mt][2] = __float_as_uint(p[4]);
                a[mt][3] = __float_as_uint(p[8 * 20 + 4]);
            }
            #pragma unroll
            for (int nt = 0; nt < 4; nt++) {
                const float* p = &Bs[buf][kk + j][wn32 + nt * 8 + g];
                bfr[nt][0] = __float_as_uint(p[0]);
                bfr[nt][1] = __float_as_uint(p[4 * 136]);
            }
            #pragma unroll
            for (int mt = 0; mt < 4; mt++)
                #pragma unroll
                for (int nt = 0; nt < 4; nt++)
                    MMA_TF32(c[mt][nt][0], c[mt][nt][1], c[mt][nt][2], c[mt][nt][3],
                             a[mt][0], a[mt][1], a[mt][2], a[mt][3],
                             bfr[nt][0], bfr[nt][1]);
        }
        if (notlast) {
            int nb = buf ^ 1;
            float4 t;
            t.x = to_tf32(av0.x); t.y = to_tf32(av0.y); t.z = to_tf32(av0.z); t.w = to_tf32(av0.w);
            *(float4*)&As[nb][aRow0][aKc] = t;
            t.x = to_tf32(av1.x); t.y = to_tf32(av1.y); t.z = to_tf32(av1.z); t.w = to_tf32(av1.w);
            *(float4*)&As[nb][aRow0 + 64][aKc] = t;
            t.x = to_tf32(bv0.x); t.y = to_tf32(bv0.y); t.z = to_tf32(bv0.z); t.w = to_tf32(bv0.w);
            *(float4*)&Bs[nb][bRow0][bCc] = t;
            t.x = to_tf32(bv1.x); t.y = to_tf32(bv1.y); t.z = to_tf32(bv1.z); t.w = to_tf32(bv1.w);
            *(float4*)&Bs[nb][bRow0 + 8][bCc] = t;
            __syncthreads();
            buf = nb;
        }
    }

    // epilogue
    #pragma unroll
    for (int mt = 0; mt < 4; mt++) {
        int r0 = by * 128 + wm64 + mt * 16 + g;
        #pragma unroll
        for (int nt = 0; nt < 4; nt++) {
            int col = bx * 128 + wn32 + nt * 8 + 2 * j;
            float b0 = 0.0f, b1 = 0.0f;
            if (act >= 1) { b0 = bias[col]; b1 = bias[col + 1]; }
            float v0 = c[mt][nt][0] + b0;
            float v1 = c[mt][nt][1] + b1;
            float v2 = c[mt][nt][2] + b0;
            float v3 = c[mt][nt][3] + b1;
            if (act == 2) {
                v0 = gelu_tanh(v0); v1 = gelu_tanh(v1);
                v2 = gelu_tanh(v2); v3 = gelu_tanh(v3);
            }
            *(float2*)(C + (long long)r0 * N + col)       = make_float2(v0, v1);
            *(float2*)(C + (long long)(r0 + 8) * N + col) = make_float2(v2, v3);
        }
    }
}

// ---------------------------------------------------------------------------
// Fused attention (tensor cores): per (b,h), n-tile 64.
// S = (0.125*Q)K^T; E = exp(S) -> tmp (unnormalized); O = (E@V)/rowsum.
// No max subtraction (logits small; exact softmax identity).
// Dynamic smem: Qs(64x68) Kt(64x68) Vs(64x72) Ps(64x68) sums(4x64) = 71.7KB
// ---------------------------------------------------------------------------
__global__ void __launch_bounds__(256)
att_fused(const float* __restrict__ q, const float* __restrict__ kv,
          float* __restrict__ tmp, float* __restrict__ rowrl,
          float* __restrict__ attout)
{
    int bh = blockIdx.y;
    int b = bh >> 4, h = bh & 15;
    int n0 = blockIdx.x * 64;

    float* Qs   = dynsm;            // [n][d] pad 68
    float* Kt   = dynsm + 4352;     // [m][d] pad 68
    float* Vs   = dynsm + 8704;     // [m][d] pad 72
    float* Ps   = dynsm + 13312;    // [n][m] pad 68
    float* sums = dynsm + 17664;    // [4][64]

    int tid = threadIdx.x, lane = tid & 31, wid = tid >> 5;
    int g = lane >> 2, j = lane & 3;
    int wm32 = (wid >> 2) * 32;
    int wn16 = (wid & 3) * 16;

    sums[tid & 255] = 0.0f;

    for (int i = tid; i < 1024; i += 256) {
        int r = i >> 4, c4 = (i & 15) * 4;
        float4 v = *(const float4*)(q + ((size_t)(b * 1024 + n0 + r) * 1024) + h * 64 + c4);
        float4 t;
        t.x = to_tf32(v.x * 0.125f); t.y = to_tf32(v.y * 0.125f);
        t.z = to_tf32(v.z * 0.125f); t.w = to_tf32(v.w * 0.125f);
        *(float4*)&Qs[r * 68 + c4] = t;
    }

    float o[2][2][4];
    #pragma unroll
    for (int mt = 0; mt < 2; mt++)
        #pragma unroll
        for (int nt = 0; nt < 2; nt++)
            #pragma unroll
            for (int r = 0; r < 4; r++) o[mt][nt][r] = 0.0f;

    for (int m0 = 0; m0 < 1024; m0 += 64) {
        __syncthreads();
        for (int i = tid; i < 1024; i += 256) {
            int r = i >> 4, c4 = (i & 15) * 4;
            const float* kb = kv + ((size_t)(b * 1024 + m0 + r) * 2048) + h * 64 + c4;
            float4 kvv = *(const float4*)kb;
            float4 t;
            t.x = to_tf32(kvv.x); t.y = to_tf32(kvv.y);
            t.z = to_tf32(kvv.z); t.w = to_tf32(kvv.w);
            *(float4*)&Kt[r * 68 + c4] = t;
            float4 vv = *(const float4*)(kb + 1024);
            t.x = to_tf32(vv.x); t.y = to_tf32(vv.y);
            t.z = to_tf32(vv.z); t.w = to_tf32(vv.w);
            *(float4*)&Vs[r * 72 + c4] = t;
        }
        __syncthreads();

        // S-mma
        float c[2][2][4];
        #pragma unroll
        for (int mt = 0; mt < 2; mt++)
            #pragma unroll
            for (int nt = 0; nt < 2; nt++)
                #pragma unroll
                for (int r = 0; r < 4; r++) c[mt][nt][r] = 0.0f;

        #pragma unroll
        for (int kk = 0; kk < 64; kk += 8) {
            uint32_t a[2][4], bf[2][2];
            #pragma unroll
            for (int mt = 0; mt < 2; mt++) {
                const float* p = &Qs[(wm32 + mt * 16 + g) * 68 + kk + j];
                a[mt][0] = __float_as_uint(p[0]);
                a[mt][1] = __float_as_uint(p[8 * 68]);
                a[mt][2] = __float_as_uint(p[4]);
                a[mt][3] = __float_as_uint(p[8 * 68 + 4]);
            }
            #pragma unroll
            for (int nt = 0; nt < 2; nt++) {
                const float* p = &Kt[(wn16 + nt * 8 + g) * 68 + kk + j];
                bf[nt][0] = __float_as_uint(p[0]);
                bf[nt][1] = __float_as_uint(p[4]);
            }
            #pragma unroll
            for (int mt = 0; mt < 2; mt++)
                #pragma unroll
                for (int nt = 0; nt < 2; nt++)
                    MMA_TF32(c[mt][nt][0], c[mt][nt][1], c[mt][nt][2], c[mt][nt][3],
                             a[mt][0], a[mt][1], a[mt][2], a[mt][3],
                             bf[nt][0], bf[nt][1]);
        }

        // E = exp(S): write tmp + Ps, accumulate row sums
        #pragma unroll
        for (int mt = 0; mt < 2; mt++) {
            int r1 = wm32 + mt * 16 + g;
            float eA = 0.0f, eB = 0.0f;
            #pragma unroll
            for (int nt = 0; nt < 2; nt++) {
                int col = wn16 + nt * 8 + 2 * j;
                float e0 = __expf(c[mt][nt][0]);
                float e1 = __expf(c[mt][nt][1]);
                float e2 = __expf(c[mt][nt][2]);
                float e3 = __expf(c[mt][nt][3]);
                float* base = tmp + ((size_t)bh * 1024 + n0 + r1) * 1024 + m0 + col;
                *(float2*)base              = make_float2(e0, e1);
                *(float2*)(base + 8 * 1024) = make_float2(e2, e3);
                *(float2*)&Ps[r1 * 68 + col]       = make_float2(to_tf32(e0), to_tf32(e1));
                *(float2*)&Ps[(r1 + 8) * 68 + col] = make_float2(to_tf32(e2), to_tf32(e3));
                eA += e0 + e1;
                eB += e2 + e3;
            }
            eA += __shfl_xor_sync(0xffffffffu, eA, 1);
            eA += __shfl_xor_sync(0xffffffffu, eA, 2);
            eB += __shfl_xor_sync(0xffffffffu, eB, 1);
            eB += __shfl_xor_sync(0xffffffffu, eB, 2);
            if (j == 0) {
                sums[(wn16 >> 4) * 64 + r1]     += eA;
                sums[(wn16 >> 4) * 64 + r1 + 8] += eB;
            }
        }
        __syncthreads();

        // PV-mma: A = Ps (E), B = Vs
        #pragma unroll
        for (int kk = 0; kk < 64; kk += 8) {
            uint32_t a[2][4], bf[2][2];
            #pragma unroll
            for (int mt = 0; mt < 2; mt++) {
                const float* p = &Ps[(wm32 + mt * 16 + g) * 68 + kk + j];
                a[mt][0] = __float_as_uint(p[0]);
                a[mt][1] = __float_as_uint(p[8 * 68]);
                a[mt][2] = __float_as_uint(p[4]);
                a[mt][3] = __float_as_uint(p[8 * 68 + 4]);
            }
            #pragma unroll
            for (int nt = 0; nt < 2; nt++) {
                const float* p = &Vs[(kk + j) * 72 + wn16 + nt * 8 + g];
                bf[nt][0] = __float_as_uint(p[0]);
                bf[nt][1] = __float_as_uint(p[4 * 72]);
            }
            #pragma unroll
            for (int mt = 0; mt < 2; mt++)
                #pragma unroll
                for (int nt = 0; nt < 2; nt++)
                    MMA_TF32(o[mt][nt][0], o[mt][nt][1], o[mt][nt][2], o[mt][nt][3],
                             a[mt][0], a[mt][1], a[mt][2], a[mt][3],
                             bf[nt][0], bf[nt][1]);
        }
    }

    __syncthreads();
    if (tid < 64) {
        float tot = sums[tid] + sums[64 + tid] + sums[128 + tid] + sums[192 + tid];
        float r = 1.0f / tot;
        sums[tid] = r;                                 // reuse as reciprocal
        rowrl[(size_t)bh * 1024 + n0 + tid] = r;
    }
    __syncthreads();

    #pragma unroll
    for (int mt = 0; mt < 2; mt++) {
        int r1 = wm32 + mt * 16 + g;
        float rlA = sums[r1], rlB = sums[r1 + 8];
        #pragma unroll
        for (int nt = 0; nt < 2; nt++) {
            int col = wn16 + nt * 8 + 2 * j;
            float* base = attout + ((size_t)(b * 1024 + n0 + r1) * 1024) + h * 64 + col;
            *(float2*)base              = make_float2(o[mt][nt][0] * rlA, o[mt][nt][1] * rlA);
            *(float2*)(base + 8 * 1024) = make_float2(o[mt][nt][2] * rlB, o[mt][nt][3] * rlB);
        }
    }
}

// ---------------------------------------------------------------------------
// Normalize + transpose: out(b,n,m,h) = E(b,h,n,m) * rl(b,h,n).
// ---------------------------------------------------------------------------
__global__ void attn_tr(const float* __restrict__ tmp, const float* __restrict__ rowrl,
                        float* __restrict__ outAttn)
{
    int b = blockIdx.z;
    int n = blockIdx.y;
    int m0 = blockIdx.x * 256;
    __shared__ float T[16][257];
    __shared__ float rl_s[16];
    int tid = threadIdx.x;
    if (tid < 16) rl_s[tid] = rowrl[(size_t)(b * 16 + tid) * 1024 + n];
    __syncthreads();
    for (int i = tid; i < 16 * 256; i += 256) {
        int hh = i >> 8, mm = i & 255;
        T[hh][mm] = tmp[((size_t)(b * 16 + hh) * 1024 + n) * 1024 + m0 + mm] * rl_s[hh];
    }
    __syncthreads();
    float* dst = outAttn + ((size_t)(b * 1024 + n) * 1024 + m0 + tid) * 16;
    #pragma unroll
    for (int k = 0; k < 16; k += 4) {
        *(float4*)(dst + k) = make_float4(T[k][tid], T[k + 1][tid], T[k + 2][tid], T[k + 3][tid]);
    }
}

// ---------------------------------------------------------------------------
// Row softmax over contiguous 1024 (combine weights).
// ---------------------------------------------------------------------------
__global__ void row_softmax(const float* __restrict__ in, float* __restrict__ outp)
{
    size_t row = blockIdx.x;
    const float4* L = (const float4*)(in + row * 1024);
    float4* O = (float4*)(outp + row * 1024);
    int t = threadIdx.x;
    float4 v = L[t];
    float mx = fmaxf(fmaxf(v.x, v.y), fmaxf(v.z, v.w));
    __shared__ float smA[8], smB[8];
    #pragma unroll
    for (int off = 16; off; off >>= 1) mx = fmaxf(mx, __shfl_xor_sync(0xffffffffu, mx, off));
    if ((t & 31) == 0) smA[t >> 5] = mx;
    __syncthreads();
    mx = smA[0];
    #pragma unroll
    for (int w = 1; w < 8; w++) mx = fmaxf(mx, smA[w]);
    float e0 = __expf(v.x - mx), e1 = __expf(v.y - mx);
    float e2 = __expf(v.z - mx), e3 = __expf(v.w - mx);
    float s = e0 + e1 + e2 + e3;
    #pragma unroll
    for (int off = 16; off; off >>= 1) s += __shfl_xor_sync(0xffffffffu, s, off);
    if ((t & 31) == 0) smB[t >> 5] = s;
    __syncthreads();
    s = 0.0f;
    #pragma unroll
    for (int w = 0; w < 8; w++) s += smB[w];
    float r = 1.0f / s;
    O[t] = make_float4(e0 * r, e1 * r, e2 * r, e3 * r);
}

// ---------------------------------------------------------------------------
// Dispatch softmax over token axis n, written TRANSPOSED: dispT[b][es][n].
// ---------------------------------------------------------------------------
__global__ void disp_softmax(const float* __restrict__ logits, float* __restrict__ dispT)
{
    int b = blockIdx.y;
    int c0 = blockIdx.x * 64;
    const float* L = logits + (size_t)b * 1048576;
    float* O = dispT + (size_t)b * 1048576;
    int tid = threadIdx.x;
    int tx = tid & 63, ty = tid >> 6;   // 4 x 64
    int col = c0 + tx;

    __shared__ float red[4][64];
    float mx = -1e30f;
    for (int n = ty; n < 1024; n += 4) mx = fmaxf(mx, L[(size_t)n * 1024 + col]);
    red[ty][tx] = mx;
    __syncthreads();
    mx = fmaxf(fmaxf(red[0][tx], red[1][tx]), fmaxf(red[2][tx], red[3][tx]));
    __syncthreads();
    float s = 0.0f;
    for (int n = ty; n < 1024; n += 4) s += __expf(L[(size_t)n * 1024 + col] - mx);
    red[ty][tx] = s;
    __syncthreads();
    s = red[0][tx] + red[1][tx] + red[2][tx] + red[3][tx];
    float rinv = 1.0f / s;
    __syncthreads();

    __shared__ float T[64][65];
    for (int n0 = 0; n0 < 1024; n0 += 64) {
        for (int n = ty; n < 64; n += 4)
            T[tx][n] = __expf(L[(size_t)(n0 + n) * 1024 + col] - mx) * rinv;
        __syncthreads();
        int cl = tid >> 2;
        int nl = (tid & 3) * 16;
        float* dst = O + (size_t)(c0 + cl) * 1024 + n0 + nl;
        #pragma unroll
        for (int k = 0; k < 16; k += 4)
            *(float4*)(dst + k) = make_float4(T[cl][nl + k], T[cl][nl + k + 1],
                                              T[cl][nl + k + 2], T[cl][nl + k + 3]);
        __syncthreads();
    }
}

// ---------------------------------------------------------------------------
// Fused residual + LayerNorm: out = LN(a + coefb * bsrc) * g + beta
// ---------------------------------------------------------------------------
__global__ void ln_res(const float* __restrict__ a, const float* __restrict__ bsrc,
                       float coefb, const float* __restrict__ g,
                       const float* __restrict__ beta, float* __restrict__ outp)
{
    size_t row = blockIdx.x;
    int t = threadIdx.x;
    float4 av = ((const float4*)(a + row * 1024))[t];
    float4 bv = ((const float4*)(bsrc + row * 1024))[t];
    float x0 = av.x + coefb * bv.x;
    float x1 = av.y + coefb * bv.y;
    float x2 = av.z + coefb * bv.z;
    float x3 = av.w + coefb * bv.w;
    float s = x0 + x1 + x2 + x3;
    float q = x0 * x0 + x1 * x1 + x2 * x2 + x3 * x3;
    __shared__ float smA[8], smB[8];
    #pragma unroll
    for (int off = 16; off; off >>= 1) {
        s += __shfl_xor_sync(0xffffffffu, s, off);
        q += __shfl_xor_sync(0xffffffffu, q, off);
    }
    if ((t & 31) == 0) { smA[t >> 5] = s; smB[t >> 5] = q; }
    __syncthreads();
    s = 0.0f; q = 0.0f;
    #pragma unroll
    for (int w = 0; w < 8; w++) { s += smA[w]; q += smB[w]; }
    float mu = s * (1.0f / 1024.0f);
    float var = q * (1.0f / 1024.0f) - mu * mu;
    float rs = rsqrtf(var + 1e-5f);
    float4 gv = ((const float4*)g)[t];
    float4 btv = ((const float4*)beta)[t];
    float4 out4;
    out4.x = (x0 - mu) * rs * gv.x + btv.x;
    out4.y = (x1 - mu) * rs * gv.y + btv.y;
    out4.z = (x2 - mu) * rs * gv.z + btv.z;
    out4.w = (x3 - mu) * rs * gv.w + btv.w;
    ((float4*)(outp + row * 1024))[t] = out4;
}

// ---------------------------------------------------------------------------
// Launcher
// ---------------------------------------------------------------------------
extern "C" void kernel_launch(void* const* d_in, const int* in_sizes, int n_in,
                              void* d_out, int out_size)
{
    const float* x   = (const float*)d_in[0];
    const float* Wq  = (const float*)d_in[1];
    const float* bq  = (const float*)d_in[2];
    const float* Wkv = (const float*)d_in[3];
    const float* bkv = (const float*)d_in[4];
    const float* Wp  = (const float*)d_in[5];
    const float* bp  = (const float*)d_in[6];
    const float* g1  = (const float*)d_in[7];
    const float* b1  = (const float*)d_in[8];
    const float* phi = (const float*)d_in[9];
    const float* We1 = (const float*)d_in[10];
    const float* be1 = (const float*)d_in[11];
    const float* We2 = (const float*)d_in[12];
    const float* be2 = (const float*)d_in[13];
    const float* g2  = (const float*)d_in[14];
    const float* b2  = (const float*)d_in[15];

    float* arena = nullptr;
    cudaGetSymbolAddress((void**)&arena, g_arena);

    float* q      = arena + OFF_Q;
    float* kvb    = arena + OFF_KV;
    float* tmp    = arena + OFF_TMP;
    float* attout = arena + OFF_ATTOUT;
    float* proj   = arena + OFF_PROJ;
    float* x1     = arena + OFF_X1;
    float* logits = arena + OFF_LOGITS;
    float* dispT  = arena + OFF_DISPT;
    float* comb   = arena + OFF_COMB;
    float* slots  = arena + OFF_SLOTS;
    float* hbuf   = arena + OFF_H;
    float* ymoe   = arena + OFF_YMOE;
    float* moeout = arena + OFF_MOE;
    float* rl     = arena + OFF_RL;

    float* out = (float*)d_out;
    float* outAttn = out + 4194304;

    const int ATT_SMEM = 71680;   // Qs+Kt+Vs+Ps+sums
    cudaFuncSetAttribute(att_fused, cudaFuncAttributeMaxDynamicSharedMemorySize, ATT_SMEM);

    dim3 T(256);

    // q = x @ Wq + bq          (4096x1024x1024)
    tgemm<<<dim3(8, 32, 1), T>>>(x, Wq, bq, q, 4096, 1024, 1024, 0, 0, 0, 0, 1, 1);
    // kv = x @ Wkv + bkv       (4096x2048x1024)
    tgemm<<<dim3(16, 32, 1), T>>>(x, Wkv, bkv, kvb, 4096, 2048, 1024, 0, 0, 0, 0, 1, 1);

    // fused attention + transpose
    att_fused<<<dim3(16, 64), T, ATT_SMEM>>>(q, kvb, tmp, rl, attout);
    attn_tr<<<dim3(4, 1024, 4), T>>>(tmp, rl, outAttn);

    // out-proj + residual LN
    tgemm<<<dim3(8, 32, 1), T>>>(attout, Wp, bp, proj, 4096, 1024, 1024, 0, 0, 0, 0, 1, 1);
    ln_res<<<4096, T>>>(proj, x, 1.0f, g1, b1, x1);

    // soft-MoE
    tgemm<<<dim3(8, 32, 1), T>>>(x1, phi, nullptr, logits, 4096, 1024, 1024, 0, 0, 0, 0, 1, 0);
    row_softmax<<<4096, T>>>(logits, comb);
    disp_softmax<<<dim3(16, 4), T>>>(logits, dispT);

    // slots[b] = dispT[b] @ x1[b]
    tgemm<<<dim3(8, 8, 4), T>>>(dispT, x1, nullptr, slots, 1024, 1024, 1024,
                                1048576, 1048576, 0, 1048576, 0, 0);
    // h = gelu(slots @ We1[e] + be1[e])
    tgemm<<<dim3(32, 4, 8), T>>>(slots, We1, be1, hbuf, 512, 4096, 1024,
                                 524288, 4194304, 4096, 2097152, 2, 2);
    // y = h @ We2[e] + be2[e]
    tgemm<<<dim3(8, 4, 8), T>>>(hbuf, We2, be2, ymoe, 512, 1024, 4096,
                                2097152, 4194304, 1024, 524288, 2, 1);
    // moe_out[b] = comb[b] @ ymoe[b]
    tgemm<<<dim3(8, 8, 4), T>>>(comb, ymoe, nullptr, moeout, 1024, 1024, 1024,
                                1048576, 1048576, 0, 1048576, 0, 0);

    // y = LN(moe_out + 2*x1)
    ln_res<<<4096, T>>>(moeout, x1, 2.0f, g2, b2, out);
}

// round 6
// speedup vs baseline: 2.2377x; 1.1599x over previous
#include <cuda_runtime.h>
#include <cuda_fp16.h>
#include <math.h>
#include <stdint.h>

// ---------------------------------------------------------------------------
// Problem constants
//   B=4, SEQ=1024, DIM=1024, HEADS=16, HD=64, N_EXP=2, SLOTS=512, HID=4096
// Output: [ y : 4*1024*1024 f32 ][ attn : 4*1024*1024*16 f32 ]
// ---------------------------------------------------------------------------

#define OFF_Q       0LL
#define OFF_KV      4194304LL
#define OFF_TMP     12582912LL     // attn E=exp(S) scratch, fp16 (b,h,n,m) 64M halves
#define OFF_ATTOUT  79691776LL
#define OFF_PROJ    83886080LL
#define OFF_X1      88080384LL
#define OFF_LOGITS  92274688LL
#define OFF_DISPT   96468992LL
#define OFF_COMB    100663296LL
#define OFF_SLOTS   104857600LL
#define OFF_H       109051904LL    // 16M floats
#define OFF_YMOE    125829120LL
#define OFF_MOE     130023424LL
#define OFF_RL      134283264LL
#define ARENA_FLOATS 134348800LL

__device__ float g_arena[ARENA_FLOATS];

__device__ __forceinline__ float gelu_tanh(float v) {
    const float c0 = 0.7978845608028654f;   // sqrt(2/pi)
    float t = tanhf(c0 * (v + 0.044715f * v * v * v));
    return 0.5f * v * (1.0f + t);
}

__device__ __forceinline__ uint32_t smem_u32(const void* p) {
    return (uint32_t)__cvta_generic_to_shared(p);
}

#define CP16(dst, src) \
    asm volatile("cp.async.cg.shared.global [%0], [%1], 16;" :: "r"(dst), "l"(src))
#define CP_COMMIT() asm volatile("cp.async.commit_group;")
#define CP_WAIT0()  asm volatile("cp.async.wait_group 0;")

#define MMA_TF32(c0,c1,c2,c3,a0,a1,a2,a3,b0,b1)                               \
    asm volatile("mma.sync.aligned.m16n8k8.row.col.f32.tf32.tf32.f32 "        \
                 "{%0,%1,%2,%3},{%4,%5,%6,%7},{%8,%9},{%0,%1,%2,%3};"         \
                 : "+f"(c0), "+f"(c1), "+f"(c2), "+f"(c3)                     \
                 : "r"(a0), "r"(a1), "r"(a2), "r"(a3), "r"(b0), "r"(b1))

extern __shared__ float dynsm[];

// ---------------------------------------------------------------------------
// tf32 tensor-core batched GEMM, cp.async double-buffered smem, raw f32
// operands (HW truncation to tf32). C = A(MxK) @ B(KxN) [+bias] [gelu].
// M,N mult of 128, K mult of 16. 8 warps (2x4), warp tile 64x32, m16n8k8.
// ---------------------------------------------------------------------------
__global__ void __launch_bounds__(256, 2)
tgemm(const float* __restrict__ A, const float* __restrict__ Bm,
      const float* __restrict__ bias, float* __restrict__ C,
      int M, int N, int K,
      long long sA, long long sB, long long sBias, long long sC,
      int nBmod, int act)
{
    int z = blockIdx.z;
    int zb = nBmod ? (z % nBmod) : z;
    A  += (long long)z * sA;
    Bm += (long long)zb * sB;
    if (act >= 1) bias += (long long)zb * sBias;
    C  += (long long)z * sC;

    __shared__ float As[2][128][20];   // [m][k16 pad 20]
    __shared__ float Bs[2][16][136];   // [k][n128 pad 136]

    int bx = blockIdx.x, by = blockIdx.y;
    int tid = threadIdx.x;
    int wid = tid >> 5;
    int lane = tid & 31;
    int g = lane >> 2;
    int j = lane & 3;
    int wm64 = (wid >> 2) * 64;
    int wn32 = (wid & 3) * 32;

    int aRow0 = tid >> 2;            // 0..63
    int aKc   = (tid & 3) * 4;       // 0,4,8,12
    int bRow0 = tid >> 5;            // 0..7
    int bCc   = (tid & 31) * 4;      // 0..124

    const float* Ap0 = A + (long long)(by * 128 + aRow0)      * K + aKc;
    const float* Ap1 = A + (long long)(by * 128 + aRow0 + 64) * K + aKc;
    const float* Bp0 = Bm + (long long)(bRow0)     * N + bx * 128 + bCc;
    const float* Bp1 = Bm + (long long)(bRow0 + 8) * N + bx * 128 + bCc;

    uint32_t dA0[2], dA1[2], dB0[2], dB1[2];
    #pragma unroll
    for (int bb = 0; bb < 2; bb++) {
        dA0[bb] = smem_u32(&As[bb][aRow0][aKc]);
        dA1[bb] = smem_u32(&As[bb][aRow0 + 64][aKc]);
        dB0[bb] = smem_u32(&Bs[bb][bRow0][bCc]);
        dB1[bb] = smem_u32(&Bs[bb][bRow0 + 8][bCc]);
    }

    float c[4][4][4];
    #pragma unroll
    for (int mt = 0; mt < 4; mt++)
        #pragma unroll
        for (int nt = 0; nt < 4; nt++)
            #pragma unroll
            for (int r = 0; r < 4; r++) c[mt][nt][r] = 0.0f;

    // issue tile 0
    CP16(dA0[0], Ap0); CP16(dA1[0], Ap1);
    CP16(dB0[0], Bp0); CP16(dB1[0], Bp1);
    CP_COMMIT();

    int buf = 0;
    for (int k0 = 0; k0 < K; k0 += 16) {
        CP_WAIT0();
        __syncthreads();   // tile k visible block-wide; prior compute on buf^1 done

        bool notlast = (k0 + 16 < K);
        if (notlast) {
            Ap0 += 16; Ap1 += 16;
            Bp0 += (long long)16 * N; Bp1 += (long long)16 * N;
            int nb = buf ^ 1;
            CP16(dA0[nb], Ap0); CP16(dA1[nb], Ap1);
            CP16(dB0[nb], Bp0); CP16(dB1[nb], Bp1);
            CP_COMMIT();
        }

        #pragma unroll
        for (int kk = 0; kk < 16; kk += 8) {
            uint32_t a[4][4];
            uint32_t bfr[4][2];
            #pragma unroll
            for (int mt = 0; mt < 4; mt++) {
                const float* p = &As[buf][wm64 + mt * 16 + g][kk + j];
                a[mt][0] = __float_as_uint(p[0]);
                a[mt][1] = __float_as_uint(p[8 * 20]);
                a[mt][2] = __float_as_uint(p[4]);
                a[mt][3] = __float_as_uint(p[8 * 20 + 4]);
            }
            #pragma unroll
            for (int nt = 0; nt < 4; nt++) {
                const float* p = &Bs[buf][kk + j][wn32 + nt * 8 + g];
                bfr[nt][0] = __float_as_uint(p[0]);
                bfr[nt][1] = __float_as_uint(p[4 * 136]);
            }
            #pragma unroll
            for (int mt = 0; mt < 4; mt++)
                #pragma unroll
                for (int nt = 0; nt < 4; nt++)
                    MMA_TF32(c[mt][nt][0], c[mt][nt][1], c[mt][nt][2], c[mt][nt][3],
                             a[mt][0], a[mt][1], a[mt][2], a[mt][3],
                             bfr[nt][0], bfr[nt][1]);
        }
        buf ^= 1;
    }

    // epilogue
    #pragma unroll
    for (int mt = 0; mt < 4; mt++) {
        int r0 = by * 128 + wm64 + mt * 16 + g;
        #pragma unroll
        for (int nt = 0; nt < 4; nt++) {
            int col = bx * 128 + wn32 + nt * 8 + 2 * j;
            float b0 = 0.0f, b1 = 0.0f;
            if (act >= 1) { b0 = bias[col]; b1 = bias[col + 1]; }
            float v0 = c[mt][nt][0] + b0;
            float v1 = c[mt][nt][1] + b1;
            float v2 = c[mt][nt][2] + b0;
            float v3 = c[mt][nt][3] + b1;
            if (act == 2) {
                v0 = gelu_tanh(v0); v1 = gelu_tanh(v1);
                v2 = gelu_tanh(v2); v3 = gelu_tanh(v3);
            }
            *(float2*)(C + (long long)r0 * N + col)       = make_float2(v0, v1);
            *(float2*)(C + (long long)(r0 + 8) * N + col) = make_float2(v2, v3);
        }
    }
}

// ---------------------------------------------------------------------------
// Fused attention (tensor cores): per (b,h), n-tile 64.
// S = Q K^T (raw f32 operands); E = exp(0.125*S) -> tmp as fp16 (unnormalized);
// O = (E@V)/rowsum. No max subtraction (logits small; exact identity).
// Dynamic smem: Qs(64x68) Kt(64x68) Vs(64x72) Ps(64x68) sums(4x64) = 71.7KB
// ---------------------------------------------------------------------------
__global__ void __launch_bounds__(256)
att_fused(const float* __restrict__ q, const float* __restrict__ kv,
          __half* __restrict__ tmp, float* __restrict__ rowrl,
          float* __restrict__ attout)
{
    int bh = blockIdx.y;
    int b = bh >> 4, h = bh & 15;
    int n0 = blockIdx.x * 64;

    float* Qs   = dynsm;            // [n][d] pad 68
    float* Kt   = dynsm + 4352;     // [m][d] pad 68
    float* Vs   = dynsm + 8704;     // [m][d] pad 72
    float* Ps   = dynsm + 13312;    // [n][m] pad 68
    float* sums = dynsm + 17664;    // [4][64]

    int tid = threadIdx.x, lane = tid & 31, wid = tid >> 5;
    int g = lane >> 2, j = lane & 3;
    int wm32 = (wid >> 2) * 32;
    int wn16 = (wid & 3) * 16;

    sums[tid & 255] = 0.0f;

    for (int i = tid; i < 1024; i += 256) {
        int r = i >> 4, c4 = (i & 15) * 4;
        *(float4*)&Qs[r * 68 + c4] =
            *(const float4*)(q + ((size_t)(b * 1024 + n0 + r) * 1024) + h * 64 + c4);
    }

    float o[2][2][4];
    #pragma unroll
    for (int mt = 0; mt < 2; mt++)
        #pragma unroll
        for (int nt = 0; nt < 2; nt++)
            #pragma unroll
            for (int r = 0; r < 4; r++) o[mt][nt][r] = 0.0f;

    for (int m0 = 0; m0 < 1024; m0 += 64) {
        __syncthreads();
        for (int i = tid; i < 1024; i += 256) {
            int r = i >> 4, c4 = (i & 15) * 4;
            const float* kb = kv + ((size_t)(b * 1024 + m0 + r) * 2048) + h * 64 + c4;
            *(float4*)&Kt[r * 68 + c4] = *(const float4*)kb;
            *(float4*)&Vs[r * 72 + c4] = *(const float4*)(kb + 1024);
        }
        __syncthreads();

        // S-mma (Q raw, K raw; HW truncates to tf32)
        float c[2][2][4];
        #pragma unroll
        for (int mt = 0; mt < 2; mt++)
            #pragma unroll
            for (int nt = 0; nt < 2; nt++)
                #pragma unroll
                for (int r = 0; r < 4; r++) c[mt][nt][r] = 0.0f;

        #pragma unroll
        for (int kk = 0; kk < 64; kk += 8) {
            uint32_t a[2][4], bf[2][2];
            #pragma unroll
            for (int mt = 0; mt < 2; mt++) {
                const float* p = &Qs[(wm32 + mt * 16 + g) * 68 + kk + j];
                a[mt][0] = __float_as_uint(p[0]);
                a[mt][1] = __float_as_uint(p[8 * 68]);
                a[mt][2] = __float_as_uint(p[4]);
                a[mt][3] = __float_as_uint(p[8 * 68 + 4]);
            }
            #pragma unroll
            for (int nt = 0; nt < 2; nt++) {
                const float* p = &Kt[(wn16 + nt * 8 + g) * 68 + kk + j];
                bf[nt][0] = __float_as_uint(p[0]);
                bf[nt][1] = __float_as_uint(p[4]);
            }
            #pragma unroll
            for (int mt = 0; mt < 2; mt++)
                #pragma unroll
                for (int nt = 0; nt < 2; nt++)
                    MMA_TF32(c[mt][nt][0], c[mt][nt][1], c[mt][nt][2], c[mt][nt][3],
                             a[mt][0], a[mt][1], a[mt][2], a[mt][3],
                             bf[nt][0], bf[nt][1]);
        }

        // E = exp(0.125*S): write tmp (fp16) + Ps, accumulate row sums
        #pragma unroll
        for (int mt = 0; mt < 2; mt++) {
            int r1 = wm32 + mt * 16 + g;
            float eA = 0.0f, eB = 0.0f;
            #pragma unroll
            for (int nt = 0; nt < 2; nt++) {
                int col = wn16 + nt * 8 + 2 * j;
                float e0 = __expf(0.125f * c[mt][nt][0]);
                float e1 = __expf(0.125f * c[mt][nt][1]);
                float e2 = __expf(0.125f * c[mt][nt][2]);
                float e3 = __expf(0.125f * c[mt][nt][3]);
                size_t idx = ((size_t)bh * 1024 + n0 + r1) * 1024 + m0 + col;
                *(__half2*)(tmp + idx)            = __floats2half2_rn(e0, e1);
                *(__half2*)(tmp + idx + 8 * 1024) = __floats2half2_rn(e2, e3);
                *(float2*)&Ps[r1 * 68 + col]       = make_float2(e0, e1);
                *(float2*)&Ps[(r1 + 8) * 68 + col] = make_float2(e2, e3);
                eA += e0 + e1;
                eB += e2 + e3;
            }
            eA += __shfl_xor_sync(0xffffffffu, eA, 1);
            eA += __shfl_xor_sync(0xffffffffu, eA, 2);
            eB += __shfl_xor_sync(0xffffffffu, eB, 1);
            eB += __shfl_xor_sync(0xffffffffu, eB, 2);
            if (j == 0) {
                sums[(wn16 >> 4) * 64 + r1]     += eA;
                sums[(wn16 >> 4) * 64 + r1 + 8] += eB;
            }
        }
        __syncthreads();

        // PV-mma: A = Ps (E raw), B = Vs (raw)
        #pragma unroll
        for (int kk = 0; kk < 64; kk += 8) {
            uint32_t a[2][4], bf[2][2];
            #pragma unroll
            for (int mt = 0; mt < 2; mt++) {
                const float* p = &Ps[(wm32 + mt * 16 + g) * 68 + kk + j];
                a[mt][0] = __float_as_uint(p[0]);
                a[mt][1] = __float_as_uint(p[8 * 68]);
                a[mt][2] = __float_as_uint(p[4]);
                a[mt][3] = __float_as_uint(p[8 * 68 + 4]);
            }
            #pragma unroll
            for (int nt = 0; nt < 2; nt++) {
                const float* p = &Vs[(kk + j) * 72 + wn16 + nt * 8 + g];
                bf[nt][0] = __float_as_uint(p[0]);
                bf[nt][1] = __float_as_uint(p[4 * 72]);
            }
            #pragma unroll
            for (int mt = 0; mt < 2; mt++)
                #pragma unroll
                for (int nt = 0; nt < 2; nt++)
                    MMA_TF32(o[mt][nt][0], o[mt][nt][1], o[mt][nt][2], o[mt][nt][3],
                             a[mt][0], a[mt][1], a[mt][2], a[mt][3],
                             bf[nt][0], bf[nt][1]);
        }
    }

    __syncthreads();
    if (tid < 64) {
        float tot = sums[tid] + sums[64 + tid] + sums[128 + tid] + sums[192 + tid];
        float r = 1.0f / tot;
        sums[tid] = r;                                 // reuse as reciprocal
        rowrl[(size_t)bh * 1024 + n0 + tid] = r;
    }
    __syncthreads();

    #pragma unroll
    for (int mt = 0; mt < 2; mt++) {
        int r1 = wm32 + mt * 16 + g;
        float rlA = sums[r1], rlB = sums[r1 + 8];
        #pragma unroll
        for (int nt = 0; nt < 2; nt++) {
            int col = wn16 + nt * 8 + 2 * j;
            float* base = attout + ((size_t)(b * 1024 + n0 + r1) * 1024) + h * 64 + col;
            *(float2*)base              = make_float2(o[mt][nt][0] * rlA, o[mt][nt][1] * rlA);
            *(float2*)(base + 8 * 1024) = make_float2(o[mt][nt][2] * rlB, o[mt][nt][3] * rlB);
        }
    }
}

// ---------------------------------------------------------------------------
// Normalize + transpose: out(b,n,m,h) = E_fp16(b,h,n,m) * rl(b,h,n).
// ---------------------------------------------------------------------------
__global__ void attn_tr(const __half* __restrict__ tmp, const float* __restrict__ rowrl,
                        float* __restrict__ outAttn)
{
    int b = blockIdx.z;
    int n = blockIdx.y;
    int m0 = blockIdx.x * 256;
    __shared__ float T[16][257];
    __shared__ float rl_s[16];
    int tid = threadIdx.x;
    if (tid < 16) rl_s[tid] = rowrl[(size_t)(b * 16 + tid) * 1024 + n];
    __syncthreads();
    for (int i = tid; i < 16 * 128; i += 256) {
        int hh = i >> 7, mm = (i & 127) * 2;
        __half2 v = *(const __half2*)(tmp + ((size_t)(b * 16 + hh) * 1024 + n) * 1024 + m0 + mm);
        float2 f = __half22float2(v);
        float rl = rl_s[hh];
        T[hh][mm]     = f.x * rl;
        T[hh][mm + 1] = f.y * rl;
    }
    __syncthreads();
    float* dst = outAttn + ((size_t)(b * 1024 + n) * 1024 + m0 + tid) * 16;
    #pragma unroll
    for (int k = 0; k < 16; k += 4) {
        *(float4*)(dst + k) = make_float4(T[k][tid], T[k + 1][tid], T[k + 2][tid], T[k + 3][tid]);
    }
}

// ---------------------------------------------------------------------------
// Row softmax over contiguous 1024 (combine weights).
// ---------------------------------------------------------------------------
__global__ void row_softmax(const float* __restrict__ in, float* __restrict__ outp)
{
    size_t row = blockIdx.x;
    const float4* L = (const float4*)(in + row * 1024);
    float4* O = (float4*)(outp + row * 1024);
    int t = threadIdx.x;
    float4 v = L[t];
    float mx = fmaxf(fmaxf(v.x, v.y), fmaxf(v.z, v.w));
    __shared__ float smA[8], smB[8];
    #pragma unroll
    for (int off = 16; off; off >>= 1) mx = fmaxf(mx, __shfl_xor_sync(0xffffffffu, mx, off));
    if ((t & 31) == 0) smA[t >> 5] = mx;
    __syncthreads();
    mx = smA[0];
    #pragma unroll
    for (int w = 1; w < 8; w++) mx = fmaxf(mx, smA[w]);
    float e0 = __expf(v.x - mx), e1 = __expf(v.y - mx);
    float e2 = __expf(v.z - mx), e3 = __expf(v.w - mx);
    float s = e0 + e1 + e2 + e3;
    #pragma unroll
    for (int off = 16; off; off >>= 1) s += __shfl_xor_sync(0xffffffffu, s, off);
    if ((t & 31) == 0) smB[t >> 5] = s;
    __syncthreads();
    s = 0.0f;
    #pragma unroll
    for (int w = 0; w < 8; w++) s += smB[w];
    float r = 1.0f / s;
    O[t] = make_float4(e0 * r, e1 * r, e2 * r, e3 * r);
}

// ---------------------------------------------------------------------------
// Dispatch softmax over token axis n, written TRANSPOSED: dispT[b][es][n].
// ---------------------------------------------------------------------------
__global__ void disp_softmax(const float* __restrict__ logits, float* __restrict__ dispT)
{
    int b = blockIdx.y;
    int c0 = blockIdx.x * 64;
    const float* L = logits + (size_t)b * 1048576;
    float* O = dispT + (size_t)b * 1048576;
    int tid = threadIdx.x;
    int tx = tid & 63, ty = tid >> 6;   // 4 x 64
    int col = c0 + tx;

    __shared__ float red[4][64];
    float mx = -1e30f;
    for (int n = ty; n < 1024; n += 4) mx = fmaxf(mx, L[(size_t)n * 1024 + col]);
    red[ty][tx] = mx;
    __syncthreads();
    mx = fmaxf(fmaxf(red[0][tx], red[1][tx]), fmaxf(red[2][tx], red[3][tx]));
    __syncthreads();
    float s = 0.0f;
    for (int n = ty; n < 1024; n += 4) s += __expf(L[(size_t)n * 1024 + col] - mx);
    red[ty][tx] = s;
    __syncthreads();
    s = red[0][tx] + red[1][tx] + red[2][tx] + red[3][tx];
    float rinv = 1.0f / s;
    __syncthreads();

    __shared__ float T[64][65];
    for (int n0 = 0; n0 < 1024; n0 += 64) {
        for (int n = ty; n < 64; n += 4)
            T[tx][n] = __expf(L[(size_t)(n0 + n) * 1024 + col] - mx) * rinv;
        __syncthreads();
        int cl = tid >> 2;
        int nl = (tid & 3) * 16;
        float* dst = O + (size_t)(c0 + cl) * 1024 + n0 + nl;
        #pragma unroll
        for (int k = 0; k < 16; k += 4)
            *(float4*)(dst + k) = make_float4(T[cl][nl + k], T[cl][nl + k + 1],
                                              T[cl][nl + k + 2], T[cl][nl + k + 3]);
        __syncthreads();
    }
}

// ---------------------------------------------------------------------------
// Fused residual + LayerNorm: out = LN(a + coefb * bsrc) * g + beta
// ---------------------------------------------------------------------------
__global__ void ln_res(const float* __restrict__ a, const float* __restrict__ bsrc,
                       float coefb, const float* __restrict__ g,
                       const float* __restrict__ beta, float* __restrict__ outp)
{
    size_t row = blockIdx.x;
    int t = threadIdx.x;
    float4 av = ((const float4*)(a + row * 1024))[t];
    float4 bv = ((const float4*)(bsrc + row * 1024))[t];
    float x0 = av.x + coefb * bv.x;
    float x1 = av.y + coefb * bv.y;
    float x2 = av.z + coefb * bv.z;
    float x3 = av.w + coefb * bv.w;
    float s = x0 + x1 + x2 + x3;
    float q = x0 * x0 + x1 * x1 + x2 * x2 + x3 * x3;
    __shared__ float smA[8], smB[8];
    #pragma unroll
    for (int off = 16; off; off >>= 1) {
        s += __shfl_xor_sync(0xffffffffu, s, off);
        q += __shfl_xor_sync(0xffffffffu, q, off);
    }
    if ((t & 31) == 0) { smA[t >> 5] = s; smB[t >> 5] = q; }
    __syncthreads();
    s = 0.0f; q = 0.0f;
    #pragma unroll
    for (int w = 0; w < 8; w++) { s += smA[w]; q += smB[w]; }
    float mu = s * (1.0f / 1024.0f);
    float var = q * (1.0f / 1024.0f) - mu * mu;
    float rs = rsqrtf(var + 1e-5f);
    float4 gv = ((const float4*)g)[t];
    float4 btv = ((const float4*)beta)[t];
    float4 out4;
    out4.x = (x0 - mu) * rs * gv.x + btv.x;
    out4.y = (x1 - mu) * rs * gv.y + btv.y;
    out4.z = (x2 - mu) * rs * gv.z + btv.z;
    out4.w = (x3 - mu) * rs * gv.w + btv.w;
    ((float4*)(outp + row * 1024))[t] = out4;
}

// ---------------------------------------------------------------------------
// Launcher
// ---------------------------------------------------------------------------
extern "C" void kernel_launch(void* const* d_in, const int* in_sizes, int n_in,
                              void* d_out, int out_size)
{
    const float* x   = (const float*)d_in[0];
    const float* Wq  = (const float*)d_in[1];
    const float* bq  = (const float*)d_in[2];
    const float* Wkv = (const float*)d_in[3];
    const float* bkv = (const float*)d_in[4];
    const float* Wp  = (const float*)d_in[5];
    const float* bp  = (const float*)d_in[6];
    const float* g1  = (const float*)d_in[7];
    const float* b1  = (const float*)d_in[8];
    const float* phi = (const float*)d_in[9];
    const float* We1 = (const float*)d_in[10];
    const float* be1 = (const float*)d_in[11];
    const float* We2 = (const float*)d_in[12];
    const float* be2 = (const float*)d_in[13];
    const float* g2  = (const float*)d_in[14];
    const float* b2  = (const float*)d_in[15];

    float* arena = nullptr;
    cudaGetSymbolAddress((void**)&arena, g_arena);

    float* q      = arena + OFF_Q;
    float* kvb    = arena + OFF_KV;
    __half* tmp   = (__half*)(arena + OFF_TMP);
    float* attout = arena + OFF_ATTOUT;
    float* proj   = arena + OFF_PROJ;
    float* x1     = arena + OFF_X1;
    float* logits = arena + OFF_LOGITS;
    float* dispT  = arena + OFF_DISPT;
    float* comb   = arena + OFF_COMB;
    float* slots  = arena + OFF_SLOTS;
    float* hbuf   = arena + OFF_H;
    float* ymoe   = arena + OFF_YMOE;
    float* moeout = arena + OFF_MOE;
    float* rl     = arena + OFF_RL;

    float* out = (float*)d_out;
    float* outAttn = out + 4194304;

    const int ATT_SMEM = 71680;   // Qs+Kt+Vs+Ps+sums
    cudaFuncSetAttribute(att_fused, cudaFuncAttributeMaxDynamicSharedMemorySize, ATT_SMEM);

    dim3 T(256);

    // q = x @ Wq + bq          (4096x1024x1024)
    tgemm<<<dim3(8, 32, 1), T>>>(x, Wq, bq, q, 4096, 1024, 1024, 0, 0, 0, 0, 1, 1);
    // kv = x @ Wkv + bkv       (4096x2048x1024)
    tgemm<<<dim3(16, 32, 1), T>>>(x, Wkv, bkv, kvb, 4096, 2048, 1024, 0, 0, 0, 0, 1, 1);

    // fused attention + transpose
    att_fused<<<dim3(16, 64), T, ATT_SMEM>>>(q, kvb, tmp, rl, attout);
    attn_tr<<<dim3(4, 1024, 4), T>>>(tmp, rl, outAttn);

    // out-proj + residual LN
    tgemm<<<dim3(8, 32, 1), T>>>(attout, Wp, bp, proj, 4096, 1024, 1024, 0, 0, 0, 0, 1, 1);
    ln_res<<<4096, T>>>(proj, x, 1.0f, g1, b1, x1);

    // soft-MoE
    tgemm<<<dim3(8, 32, 1), T>>>(x1, phi, nullptr, logits, 4096, 1024, 1024, 0, 0, 0, 0, 1, 0);
    row_softmax<<<4096, T>>>(logits, comb);
    disp_softmax<<<dim3(16, 4), T>>>(logits, dispT);

    // slots[b] = dispT[b] @ x1[b]
    tgemm<<<dim3(8, 8, 4), T>>>(dispT, x1, nullptr, slots, 1024, 1024, 1024,
                                1048576, 1048576, 0, 1048576, 0, 0);
    // h = gelu(slots @ We1[e] + be1[e])
    tgemm<<<dim3(32, 4, 8), T>>>(slots, We1, be1, hbuf, 512, 4096, 1024,
                                 524288, 4194304, 4096, 2097152, 2, 2);
    // y = h @ We2[e] + be2[e]
    tgemm<<<dim3(8, 4, 8), T>>>(hbuf, We2, be2, ymoe, 512, 1024, 4096,
                                2097152, 4194304, 1024, 524288, 2, 1);
    // moe_out[b] = comb[b] @ ymoe[b]
    tgemm<<<dim3(8, 8, 4), T>>>(comb, ymoe, nullptr, moeout, 1024, 1024, 1024,
                                1048576, 1048576, 0, 1048576, 0, 0);

    // y = LN(moe_out + 2*x1)
    ln_res<<<4096, T>>>(moeout, x1, 2.0f, g2, b2, out);
}